// round 9
// baseline (speedup 1.0000x reference)
#include <cuda_runtime.h>
#include <cuda_fp16.h>
#include <math.h>
#include <stdint.h>

// Problem constants
#define B_   2
#define S_   2048
#define H_   2048
#define NH_  16
#define HD_  128
#define MTOT (B_ * S_)          // 4096 rows for projection GEMMs

// ---------------------------------------------------------------------------
// Device scratch (half precision operands everywhere)
// ---------------------------------------------------------------------------
__device__ __half g_q[(size_t)B_ * NH_ * S_ * HD_];
__device__ __half g_k[(size_t)B_ * NH_ * S_ * HD_];
__device__ __half g_v[(size_t)B_ * NH_ * S_ * HD_];
__device__ __half g_attn[(size_t)B_ * S_ * H_];
__device__ __half g_xh[(size_t)MTOT * H_];         // fp16 x
__device__ __half g_wt[(size_t)4 * H_ * H_];       // W^T (K-major), fp16

// ---------------------------------------------------------------------------
// Helpers
// ---------------------------------------------------------------------------
__device__ __forceinline__ uint32_t smem_u32(const void* p) {
    return (uint32_t)__cvta_generic_to_shared(p);
}
__device__ __forceinline__ void cp16(void* s, const void* g) {
    asm volatile("cp.async.cg.shared.global [%0], [%1], 16;"
                 :: "r"(smem_u32(s)), "l"(g));
}
__device__ __forceinline__ void cp_commit() {
    asm volatile("cp.async.commit_group;");
}
template <int N>
__device__ __forceinline__ void cp_wait() {
    asm volatile("cp.async.wait_group %0;" :: "n"(N));
}

__device__ __forceinline__ void ldmx4(uint32_t (&r)[4], uint32_t a) {
    asm volatile("ldmatrix.sync.aligned.m8n8.x4.shared.b16 {%0,%1,%2,%3}, [%4];"
                 : "=r"(r[0]), "=r"(r[1]), "=r"(r[2]), "=r"(r[3]) : "r"(a));
}
__device__ __forceinline__ void ldmx4t(uint32_t (&r)[4], uint32_t a) {
    asm volatile("ldmatrix.sync.aligned.m8n8.x4.trans.shared.b16 {%0,%1,%2,%3}, [%4];"
                 : "=r"(r[0]), "=r"(r[1]), "=r"(r[2]), "=r"(r[3]) : "r"(a));
}

// m16n8k16 fp16 mma, fp32 accumulate.
__device__ __forceinline__ void mma_f16(float (&c)[4], const uint32_t (&a)[4],
                                        uint32_t b0, uint32_t b1) {
    asm volatile(
        "mma.sync.aligned.m16n8k16.row.col.f32.f16.f16.f32 "
        "{%0,%1,%2,%3}, {%4,%5,%6,%7}, {%8,%9}, {%0,%1,%2,%3};\n"
        : "+f"(c[0]), "+f"(c[1]), "+f"(c[2]), "+f"(c[3])
        : "r"(a[0]), "r"(a[1]), "r"(a[2]), "r"(a[3]), "r"(b0), "r"(b1));
}

__device__ __forceinline__ uint32_t packh2(float lo, float hi) {
    __half2 h = __float22half2_rn(make_float2(lo, hi));
    return *reinterpret_cast<uint32_t*>(&h);
}

// ---------------------------------------------------------------------------
// Prep: x -> fp16; all 4 weights -> W^T fp16 (K-major) in ONE launch
// ---------------------------------------------------------------------------
__global__ void halfcast(const float* __restrict__ src, __half* __restrict__ dst,
                         int n4)
{
    int i = blockIdx.x * blockDim.x + threadIdx.x;
    if (i < n4) {
        float4 v = ((const float4*)src)[i];
        uint2 o;
        o.x = packh2(v.x, v.y);
        o.y = packh2(v.z, v.w);
        ((uint2*)dst)[i] = o;
    }
}

__global__ void transpose_half4(const float* __restrict__ W0,
                                const float* __restrict__ W1,
                                const float* __restrict__ W2,
                                const float* __restrict__ W3,
                                __half* __restrict__ Wt)
{
    const int z = blockIdx.z;
    const float* W = (z == 0) ? W0 : (z == 1) ? W1 : (z == 2) ? W2 : W3;
    __half* dst = Wt + (size_t)z * H_ * H_;

    __shared__ float t[32][33];
    int n0 = blockIdx.x * 32, k0 = blockIdx.y * 32;
    int tx = threadIdx.x, ty = threadIdx.y;
    #pragma unroll
    for (int i = 0; i < 4; i++)
        t[ty + i * 8][tx] = W[(size_t)(k0 + ty + i * 8) * H_ + n0 + tx];
    __syncthreads();
    #pragma unroll
    for (int i = 0; i < 4; i++)
        dst[(size_t)(n0 + ty + i * 8) * H_ + k0 + tx] = __float2half(t[tx][ty + i * 8]);
}

// ---------------------------------------------------------------------------
// WIDE fused QKV GEMM: CTA tile 128x256, warp tile 64x64 (2x4 warps),
// 4-stage cp.async pipeline, ONE sync per K-iter, 1 CTA/SM (255-reg budget).
// ldmatrix wavefronts per output ~2.4x lower than the 128x128 kernel.
// ---------------------------------------------------------------------------
#define GW_ROWB 80
#define GW_STGB (384 * GW_ROWB)            // A 128 + B 256 rows -> 30720 B
#define GW_STG  4
#define GW_SMEM (GW_STG * GW_STGB)         // 122880 B

__global__ __launch_bounds__(256, 1)
void gemm_wide(const __half* __restrict__ A, const __half* __restrict__ Wt,
               const float* __restrict__ b0v, const float* __restrict__ b1v,
               const float* __restrict__ b2v,
               __half* __restrict__ o0, __half* __restrict__ o1,
               __half* __restrict__ o2)
{
    constexpr int BK = 32;                 // halves per K step
    constexpr int K = H_;
    extern __shared__ char smc[];
    const uint32_t sbase = smem_u32(smc);

    const int tid = threadIdx.x;
    const int w = tid >> 5, lane = tid & 31, g = lane >> 2, t4 = lane & 3;
    const int wr = w >> 2, wc = w & 3;     // 2 x 4 warps, tile 64 x 64
    const int mBase = blockIdx.y * 128;
    const int nBase = blockIdx.x * 256;

    float acc[4][8][4] = {};

    auto loadStage = [&](int kt, int s) {
        char* St = smc + s * GW_STGB;
        const int k0 = kt * BK;
        #pragma unroll
        for (int i = 0; i < 2; i++) {      // A: 512 chunks
            int id = tid + i * 256;
            int r = id >> 2, c = id & 3;
            cp16(St + r * GW_ROWB + c * 16,
                 A + (size_t)(mBase + r) * K + k0 + c * 8);
        }
        #pragma unroll
        for (int i = 0; i < 4; i++) {      // B: 1024 chunks
            int id = tid + i * 256;
            int r = id >> 2, c = id & 3;
            cp16(St + (128 + r) * GW_ROWB + c * 16,
                 Wt + (size_t)(nBase + r) * K + k0 + c * 8);
        }
    };

    const int nIter = K / BK;   // 64
    loadStage(0, 0); cp_commit();
    loadStage(1, 1); cp_commit();
    loadStage(2, 2); cp_commit();

    const int aRow = wr * 64 + (lane & 15);
    const int aChunk = (lane >> 4) << 4;
    const int li = lane >> 3;
    const int bRowOff = ((li >> 1) << 3) + (lane & 7);
    const int bChunk = (li & 1) << 4;

    for (int kt = 0; kt < nIter; kt++) {
        cp_wait<2>();           // stage kt complete
        __syncthreads();        // + all warps done with stage (kt-1)%4

        const int nt = kt + 3;
        if (nt < nIter) loadStage(nt, nt & 3);
        cp_commit();

        const uint32_t Ab = sbase + (kt & 3) * GW_STGB;
        const uint32_t Bb = Ab + 128 * GW_ROWB;

        #pragma unroll
        for (int k16 = 0; k16 < 2; k16++) {
            uint32_t af[4][4], bf[4][4];
            #pragma unroll
            for (int mi = 0; mi < 4; mi++)
                ldmx4(af[mi], Ab + (aRow + mi * 16) * GW_ROWB + aChunk + k16 * 32);
            #pragma unroll
            for (int np = 0; np < 4; np++)
                ldmx4(bf[np], Bb + (wc * 64 + np * 16 + bRowOff) * GW_ROWB
                              + bChunk + k16 * 32);
            #pragma unroll
            for (int mi = 0; mi < 4; mi++)
                #pragma unroll
                for (int np = 0; np < 4; np++) {
                    mma_f16(acc[mi][np * 2 + 0], af[mi], bf[np][0], bf[np][1]);
                    mma_f16(acc[mi][np * 2 + 1], af[mi], bf[np][2], bf[np][3]);
                }
        }
    }

    // Epilogue: bias + fp16 scatter to [B][NH][S][HD] of Q/K/V
    #pragma unroll
    for (int mi = 0; mi < 4; mi++) {
        #pragma unroll
        for (int r2 = 0; r2 < 2; r2++) {
            const int m = mBase + wr * 64 + mi * 16 + g + r2 * 8;
            const int b = m >> 11;
            const int s = m & (S_ - 1);
            #pragma unroll
            for (int ni = 0; ni < 8; ni++) {
                const int n = nBase + wc * 64 + ni * 8 + 2 * t4;
                const int which = n >> 11;        // 0=Q 1=K 2=V
                const int n2 = n & (H_ - 1);
                const float* bias = (which == 0) ? b0v : (which == 1) ? b1v : b2v;
                __half* dst = (which == 0) ? o0 : (which == 1) ? o1 : o2;
                const int h = n2 >> 7;
                const int d = n2 & (HD_ - 1);
                uint32_t pv = packh2(acc[mi][ni][r2 * 2 + 0] + bias[n2],
                                     acc[mi][ni][r2 * 2 + 1] + bias[n2 + 1]);
                *(uint32_t*)&dst[(((size_t)(b * NH_ + h)) * S_ + s) * HD_ + d] = pv;
            }
        }
    }
}

// ---------------------------------------------------------------------------
// fp16 GEMM 128x128 (Round 7, proven) — used for the out-projection.
// ---------------------------------------------------------------------------
#define GH_ROWB 80
#define GH_STGB (256 * GH_ROWB)            // 20480 B per stage
#define GH_SMEM (3 * GH_STGB)              // 61440 B

__global__ __launch_bounds__(256, 2)
void gemm_h(const __half* __restrict__ A, const __half* __restrict__ Wt,
            const float* __restrict__ bias, float* __restrict__ of)
{
    constexpr int BK = 32;
    constexpr int K = H_;
    extern __shared__ char smc[];
    const uint32_t sbase = smem_u32(smc);

    const int tid = threadIdx.x;
    const int w = tid >> 5, lane = tid & 31, g = lane >> 2, t4 = lane & 3;
    const int wr = w >> 2, wc = w & 3;
    const int mBase = blockIdx.y * 128;
    const int nBase = blockIdx.x * 128;

    float acc[4][4][4] = {};

    auto loadStage = [&](int kt, int s) {
        char* St = smc + s * GH_STGB;
        const int k0 = kt * BK;
        #pragma unroll
        for (int i = 0; i < 2; i++) {
            int id = tid + i * 256;
            int r = id >> 2, c = id & 3;
            cp16(St + r * GH_ROWB + c * 16,
                 A + (size_t)(mBase + r) * K + k0 + c * 8);
        }
        #pragma unroll
        for (int i = 0; i < 2; i++) {
            int id = tid + i * 256;
            int r = id >> 2, c = id & 3;
            cp16(St + (128 + r) * GH_ROWB + c * 16,
                 Wt + (size_t)(nBase + r) * K + k0 + c * 8);
        }
    };

    const int nIter = K / BK;   // 64
    loadStage(0, 0); cp_commit();
    loadStage(1, 1); cp_commit();

    const int aRow = wr * 64 + (lane & 15);
    const int aChunk = (lane >> 4) << 4;
    const int li = lane >> 3;
    const int bRowOff = ((li >> 1) << 3) + (lane & 7);
    const int bChunk = (li & 1) << 4;

    for (int kt = 0; kt < nIter; kt++) {
        cp_wait<1>();
        __syncthreads();

        const int nt = kt + 2;
        if (nt < nIter) loadStage(nt, nt % 3);
        cp_commit();

        const uint32_t Ab = sbase + (kt % 3) * GH_STGB;
        const uint32_t Bb = Ab + 128 * GH_ROWB;

        #pragma unroll
        for (int k16 = 0; k16 < 2; k16++) {
            uint32_t af[4][4], bf[2][4];
            #pragma unroll
            for (int mi = 0; mi < 4; mi++)
                ldmx4(af[mi], Ab + (aRow + mi * 16) * GH_ROWB + aChunk + k16 * 32);
            #pragma unroll
            for (int np = 0; np < 2; np++)
                ldmx4(bf[np], Bb + (wc * 32 + np * 16 + bRowOff) * GH_ROWB
                              + bChunk + k16 * 32);
            #pragma unroll
            for (int mi = 0; mi < 4; mi++)
                #pragma unroll
                for (int np = 0; np < 2; np++) {
                    mma_f16(acc[mi][np * 2 + 0], af[mi], bf[np][0], bf[np][1]);
                    mma_f16(acc[mi][np * 2 + 1], af[mi], bf[np][2], bf[np][3]);
                }
        }
    }

    #pragma unroll
    for (int mi = 0; mi < 4; mi++) {
        #pragma unroll
        for (int r2 = 0; r2 < 2; r2++) {
            const int m = mBase + wr * 64 + mi * 16 + g + r2 * 8;
            #pragma unroll
            for (int ni = 0; ni < 4; ni++) {
                const int n = nBase + wc * 32 + ni * 8 + 2 * t4;
                float2 v;
                v.x = acc[mi][ni][r2 * 2 + 0] + bias[n];
                v.y = acc[mi][ni][r2 * 2 + 1] + bias[n + 1];
                *(float2*)&of[(size_t)m * H_ + n] = v;
            }
        }
    }
}

// ---------------------------------------------------------------------------
// fp16 flash attention, BKT=64, DOUBLE-BUFFERED K/V (tile kt+1 streams in
// during compute of kt). 8 warps x 16 rows, full N=64 / d=128 per warp.
// ---------------------------------------------------------------------------
#define AT_BK   64
#define AQ_ROWB 272
#define AT_KVB  (AT_BK * AQ_ROWB)                              // 17408 B
#define AT_SMEM (128 * AQ_ROWB + 4 * AT_KVB + 2 * AT_BK * 4)   // 104960 B

__global__ __launch_bounds__(256, 2)
void attn_h(const __half* __restrict__ Q, const __half* __restrict__ K,
            const __half* __restrict__ V, const float* __restrict__ mask,
            __half* __restrict__ out)
{
    extern __shared__ char smc[];
    char* Qs = smc;                              // 128 x 272 B
    char* KV = Qs + 128 * AQ_ROWB;               // 2 x (K 64x272 + V 64x272)
    float* msk = (float*)(KV + 4 * AT_KVB);      // 2 x 64 floats
    const uint32_t qbase  = smem_u32(Qs);
    const uint32_t kvbase = smem_u32(KV);

    const int tid = threadIdx.x;
    const int w = tid >> 5, lane = tid & 31, g = lane >> 2, t4 = lane & 3;
    const int bh = blockIdx.y;
    const int b  = bh >> 4;
    const int q0 = blockIdx.x * 128;

    const __half* Qg = Q + ((size_t)bh * S_ + q0) * HD_;
    const __half* Kg = K + (size_t)bh * S_ * HD_;
    const __half* Vg = V + (size_t)bh * S_ * HD_;
    const float* maskg = mask + (size_t)b * S_;

    // Q tile: 128 rows x 256 B
    #pragma unroll
    for (int i = 0; i < 8; i++) {
        int id = tid + i * 256;
        int r = id >> 4, c = id & 15;
        cp16(Qs + r * AQ_ROWB + c * 16, Qg + (size_t)r * HD_ + c * 8);
    }
    auto loadKV = [&](int kb0, int buf) {
        char* Kb = KV + buf * 2 * AT_KVB;
        char* Vb = Kb + AT_KVB;
        #pragma unroll
        for (int i = 0; i < 4; i++) {
            int id = tid + i * 256;
            int r = id >> 4, c = id & 15;
            cp16(Kb + r * AQ_ROWB + c * 16, Kg + (size_t)(kb0 + r) * HD_ + c * 8);
            cp16(Vb + r * AQ_ROWB + c * 16, Vg + (size_t)(kb0 + r) * HD_ + c * 8);
        }
        if (tid < AT_BK) msk[buf * AT_BK + tid] = maskg[kb0 + tid];
    };
    loadKV(0, 0);       cp_commit();   // G0 (incl. Q)
    loadKV(AT_BK, 1);   cp_commit();   // G1

    float O[16][4];
    #pragma unroll
    for (int nt = 0; nt < 16; nt++)
        #pragma unroll
        for (int c = 0; c < 4; c++) O[nt][c] = 0.f;
    float m_lo = -1e30f, m_hi = -1e30f, l_lo = 0.f, l_hi = 0.f;

    const float scale = 0.08838834764831845f;   // 1/sqrt(128)
    const int nIter = S_ / AT_BK;               // 32

    const int aRow = (lane & 15);
    const int aChunk = (lane >> 4) << 4;
    const int li = lane >> 3;
    const int bRowOff = ((li >> 1) << 3) + (lane & 7);
    const int bChunk = (li & 1) << 4;
    const uint32_t qaddr0 = qbase + (w * 16 + aRow) * AQ_ROWB + aChunk;

    for (int kt = 0; kt < nIter; kt++) {
        cp_wait<1>();                  // buffer kt&1 loads complete
        __syncthreads();

        const int buf = kt & 1;
        const uint32_t kbase = kvbase + buf * 2 * AT_KVB;
        const uint32_t vbase = kbase + AT_KVB;
        const float* mk = msk + buf * AT_BK;

        // ---- S = Q @ K^T (16x64 per warp), 8 k16 steps ----
        float sacc[8][4] = {};
        #pragma unroll
        for (int k16 = 0; k16 < 8; k16++) {
            uint32_t af[4], bf[4][4];
            ldmx4(af, qaddr0 + k16 * 32);
            #pragma unroll
            for (int np = 0; np < 4; np++)
                ldmx4(bf[np], kbase + (np * 16 + bRowOff) * AQ_ROWB
                              + bChunk + k16 * 32);
            #pragma unroll
            for (int np = 0; np < 4; np++) {
                mma_f16(sacc[np * 2 + 0], af, bf[np][0], bf[np][1]);
                mma_f16(sacc[np * 2 + 1], af, bf[np][2], bf[np][3]);
            }
        }

        // ---- scale + mask ----
        #pragma unroll
        for (int ni = 0; ni < 8; ni++)
            #pragma unroll
            for (int c = 0; c < 4; c++) {
                const int col = ni * 8 + 2 * t4 + (c & 1);
                sacc[ni][c] = sacc[ni][c] * scale + mk[col];
            }

        // ---- in-warp softmax ----
        float rm_lo = -1e30f, rm_hi = -1e30f;
        #pragma unroll
        for (int ni = 0; ni < 8; ni++) {
            rm_lo = fmaxf(rm_lo, fmaxf(sacc[ni][0], sacc[ni][1]));
            rm_hi = fmaxf(rm_hi, fmaxf(sacc[ni][2], sacc[ni][3]));
        }
        rm_lo = fmaxf(rm_lo, __shfl_xor_sync(0xffffffffu, rm_lo, 1));
        rm_lo = fmaxf(rm_lo, __shfl_xor_sync(0xffffffffu, rm_lo, 2));
        rm_hi = fmaxf(rm_hi, __shfl_xor_sync(0xffffffffu, rm_hi, 1));
        rm_hi = fmaxf(rm_hi, __shfl_xor_sync(0xffffffffu, rm_hi, 2));

        const float mn_lo = fmaxf(m_lo, rm_lo);
        const float mn_hi = fmaxf(m_hi, rm_hi);
        const float al_lo = __expf(m_lo - mn_lo);
        const float al_hi = __expf(m_hi - mn_hi);
        m_lo = mn_lo;
        m_hi = mn_hi;

        float sum_lo = 0.f, sum_hi = 0.f;
        #pragma unroll
        for (int ni = 0; ni < 8; ni++) {
            sacc[ni][0] = __expf(sacc[ni][0] - mn_lo);
            sacc[ni][1] = __expf(sacc[ni][1] - mn_lo);
            sacc[ni][2] = __expf(sacc[ni][2] - mn_hi);
            sacc[ni][3] = __expf(sacc[ni][3] - mn_hi);
            sum_lo += sacc[ni][0] + sacc[ni][1];
            sum_hi += sacc[ni][2] + sacc[ni][3];
        }
        sum_lo += __shfl_xor_sync(0xffffffffu, sum_lo, 1);
        sum_lo += __shfl_xor_sync(0xffffffffu, sum_lo, 2);
        sum_hi += __shfl_xor_sync(0xffffffffu, sum_hi, 1);
        sum_hi += __shfl_xor_sync(0xffffffffu, sum_hi, 2);
        l_lo = l_lo * al_lo + sum_lo;
        l_hi = l_hi * al_hi + sum_hi;

        #pragma unroll
        for (int nt = 0; nt < 16; nt++) {
            O[nt][0] *= al_lo;  O[nt][1] *= al_lo;
            O[nt][2] *= al_hi;  O[nt][3] *= al_hi;
        }

        // ---- O += P @ V ----
        #pragma unroll
        for (int kb = 0; kb < 4; kb++) {
            uint32_t af[4];
            af[0] = packh2(sacc[2 * kb][0],     sacc[2 * kb][1]);
            af[1] = packh2(sacc[2 * kb][2],     sacc[2 * kb][3]);
            af[2] = packh2(sacc[2 * kb + 1][0], sacc[2 * kb + 1][1]);
            af[3] = packh2(sacc[2 * kb + 1][2], sacc[2 * kb + 1][3]);
            #pragma unroll
            for (int t = 0; t < 8; t++) {
                uint32_t bf[4];
                ldmx4t(bf, vbase + (kb * 16 + aRow) * AQ_ROWB
                           + (2 * t) * 16 + aChunk);
                mma_f16(O[2 * t + 0], af, bf[0], bf[1]);
                mma_f16(O[2 * t + 1], af, bf[2], bf[3]);
            }
        }

        __syncthreads();               // all warps done with buf before refill
        const int nt2 = kt + 2;
        if (nt2 < nIter) loadKV(nt2 * AT_BK, buf);
        cp_commit();                   // unconditional (group accounting)
    }

    // ---- finalize ----
    const int h = bh & (NH_ - 1);
    const float inv_lo = 1.f / l_lo;
    const float inv_hi = 1.f / l_hi;
    const int q_lo = q0 + w * 16 + g;
    __half* dst_lo = out + ((size_t)b * S_ + q_lo) * H_ + h * HD_;
    __half* dst_hi = dst_lo + (size_t)8 * H_;
    #pragma unroll
    for (int nt = 0; nt < 16; nt++) {
        const int col = nt * 8 + 2 * t4;
        *(uint32_t*)&dst_lo[col] = packh2(O[nt][0] * inv_lo, O[nt][1] * inv_lo);
        *(uint32_t*)&dst_hi[col] = packh2(O[nt][2] * inv_hi, O[nt][3] * inv_hi);
    }
}

// ---------------------------------------------------------------------------
// Launch
// ---------------------------------------------------------------------------
extern "C" void kernel_launch(void* const* d_in, const int* in_sizes, int n_in,
                              void* d_out, int out_size)
{
    const float* x    = (const float*)d_in[0];
    const float* mask = (const float*)d_in[1];
    const float* Wq   = (const float*)d_in[2];
    const float* bq   = (const float*)d_in[3];
    const float* Wk   = (const float*)d_in[4];
    const float* bk   = (const float*)d_in[5];
    const float* Wv   = (const float*)d_in[6];
    const float* bv   = (const float*)d_in[7];
    const float* Wo   = (const float*)d_in[8];
    const float* bo   = (const float*)d_in[9];
    float* out = (float*)d_out;

    __half *q, *k, *v, *attn, *xh, *wt;
    cudaGetSymbolAddress((void**)&q,    g_q);
    cudaGetSymbolAddress((void**)&k,    g_k);
    cudaGetSymbolAddress((void**)&v,    g_v);
    cudaGetSymbolAddress((void**)&attn, g_attn);
    cudaGetSymbolAddress((void**)&xh,   g_xh);
    cudaGetSymbolAddress((void**)&wt,   g_wt);

    cudaFuncSetAttribute(gemm_wide,
                         cudaFuncAttributeMaxDynamicSharedMemorySize, GW_SMEM);
    cudaFuncSetAttribute(gemm_h,
                         cudaFuncAttributeMaxDynamicSharedMemorySize, GH_SMEM);
    cudaFuncSetAttribute(attn_h,
                         cudaFuncAttributeMaxDynamicSharedMemorySize, AT_SMEM);

    // Prep: x -> fp16; all 4 weights transposed in one launch
    const int nx4 = MTOT * H_ / 4;
    halfcast<<<(nx4 + 255) / 256, 256>>>(x, xh, nx4);
    transpose_half4<<<dim3(H_ / 32, H_ / 32, 4), dim3(32, 8)>>>(Wq, Wk, Wv, Wo, wt);

    const size_t wsz = (size_t)H_ * H_;

    // Fused QKV projection: wide tiles (N = 3*2048 over stacked weights)
    gemm_wide<<<dim3(3 * H_ / 256, MTOT / 128), 256, GW_SMEM>>>(
        xh, wt, bq, bk, bv, q, k, v);

    attn_h<<<dim3(S_ / 128, B_ * NH_), 256, AT_SMEM>>>(q, k, v, mask, attn);

    // Out projection (fp32 output)
    gemm_h<<<dim3(H_ / 128, MTOT / 128), 256, GH_SMEM>>>(
        attn, wt + 3 * wsz, bo, out);
}

// round 10
// speedup vs baseline: 1.1587x; 1.1587x over previous
#include <cuda_runtime.h>
#include <cuda_fp16.h>
#include <math.h>
#include <stdint.h>

// Problem constants
#define B_   2
#define S_   2048
#define H_   2048
#define NH_  16
#define HD_  128
#define MTOT (B_ * S_)          // 4096 rows for projection GEMMs

// ---------------------------------------------------------------------------
// Device scratch (half precision operands everywhere)
// ---------------------------------------------------------------------------
__device__ __half g_q[(size_t)B_ * NH_ * S_ * HD_];
__device__ __half g_k[(size_t)B_ * NH_ * S_ * HD_];
__device__ __half g_v[(size_t)B_ * NH_ * S_ * HD_];
__device__ __half g_attn[(size_t)B_ * S_ * H_];
__device__ __half g_xh[(size_t)MTOT * H_];         // fp16 x
__device__ __half g_wt[(size_t)4 * H_ * H_];       // W^T (K-major), fp16

// ---------------------------------------------------------------------------
// Helpers
// ---------------------------------------------------------------------------
__device__ __forceinline__ uint32_t smem_u32(const void* p) {
    return (uint32_t)__cvta_generic_to_shared(p);
}
__device__ __forceinline__ void cp16(void* s, const void* g) {
    asm volatile("cp.async.cg.shared.global [%0], [%1], 16;"
                 :: "r"(smem_u32(s)), "l"(g));
}
__device__ __forceinline__ void cp_commit() {
    asm volatile("cp.async.commit_group;");
}
template <int N>
__device__ __forceinline__ void cp_wait() {
    asm volatile("cp.async.wait_group %0;" :: "n"(N));
}

__device__ __forceinline__ void ldmx4(uint32_t (&r)[4], uint32_t a) {
    asm volatile("ldmatrix.sync.aligned.m8n8.x4.shared.b16 {%0,%1,%2,%3}, [%4];"
                 : "=r"(r[0]), "=r"(r[1]), "=r"(r[2]), "=r"(r[3]) : "r"(a));
}
__device__ __forceinline__ void ldmx4t(uint32_t (&r)[4], uint32_t a) {
    asm volatile("ldmatrix.sync.aligned.m8n8.x4.trans.shared.b16 {%0,%1,%2,%3}, [%4];"
                 : "=r"(r[0]), "=r"(r[1]), "=r"(r[2]), "=r"(r[3]) : "r"(a));
}

// m16n8k16 fp16 mma, fp32 accumulate.
__device__ __forceinline__ void mma_f16(float (&c)[4], const uint32_t (&a)[4],
                                        uint32_t b0, uint32_t b1) {
    asm volatile(
        "mma.sync.aligned.m16n8k16.row.col.f32.f16.f16.f32 "
        "{%0,%1,%2,%3}, {%4,%5,%6,%7}, {%8,%9}, {%0,%1,%2,%3};\n"
        : "+f"(c[0]), "+f"(c[1]), "+f"(c[2]), "+f"(c[3])
        : "r"(a[0]), "r"(a[1]), "r"(a[2]), "r"(a[3]), "r"(b0), "r"(b1));
}

__device__ __forceinline__ uint32_t packh2(float lo, float hi) {
    __half2 h = __float22half2_rn(make_float2(lo, hi));
    return *reinterpret_cast<uint32_t*>(&h);
}

// ---------------------------------------------------------------------------
// Prep: x -> fp16; all 4 weights -> W^T fp16 (K-major) in ONE launch
// ---------------------------------------------------------------------------
__global__ void halfcast(const float* __restrict__ src, __half* __restrict__ dst,
                         int n4)
{
    int i = blockIdx.x * blockDim.x + threadIdx.x;
    if (i < n4) {
        float4 v = ((const float4*)src)[i];
        uint2 o;
        o.x = packh2(v.x, v.y);
        o.y = packh2(v.z, v.w);
        ((uint2*)dst)[i] = o;
    }
}

__global__ void transpose_half4(const float* __restrict__ W0,
                                const float* __restrict__ W1,
                                const float* __restrict__ W2,
                                const float* __restrict__ W3,
                                __half* __restrict__ Wt)
{
    const int z = blockIdx.z;
    const float* W = (z == 0) ? W0 : (z == 1) ? W1 : (z == 2) ? W2 : W3;
    __half* dst = Wt + (size_t)z * H_ * H_;

    __shared__ float t[32][33];
    int n0 = blockIdx.x * 32, k0 = blockIdx.y * 32;
    int tx = threadIdx.x, ty = threadIdx.y;
    #pragma unroll
    for (int i = 0; i < 4; i++)
        t[ty + i * 8][tx] = W[(size_t)(k0 + ty + i * 8) * H_ + n0 + tx];
    __syncthreads();
    #pragma unroll
    for (int i = 0; i < 4; i++)
        dst[(size_t)(n0 + ty + i * 8) * H_ + k0 + tx] = __float2half(t[tx][ty + i * 8]);
}

// ---------------------------------------------------------------------------
// fp16 GEMM 128x128 warp-tile 64x32 (PROVEN shape, 2 CTAs/SM), now BK=64:
// halves iteration count -> halves syncs/waits; identical regs & math order.
// Row stride 144 B (144 mod 128 = 16 -> 8-row ldmatrix phases conflict-free).
// 3-stage cp.async pipeline, prefetch distance 2.
// ---------------------------------------------------------------------------
#define GH_ROWB 144
#define GH_STGB (256 * GH_ROWB)            // 36864 B per stage (A 128 + B 128 rows)
#define GH_SMEM (3 * GH_STGB)              // 110592 B
#define GH_BK   64

template <bool FUSED>
__global__ __launch_bounds__(256, 2)
void gemm_h(const __half* __restrict__ A, const __half* __restrict__ Wt,
            const float* __restrict__ b0v, const float* __restrict__ b1v,
            const float* __restrict__ b2v,
            __half* __restrict__ o0, __half* __restrict__ o1,
            __half* __restrict__ o2, float* __restrict__ of)
{
    constexpr int K = H_;
    extern __shared__ char smc[];
    const uint32_t sbase = smem_u32(smc);

    const int tid = threadIdx.x;
    const int w = tid >> 5, lane = tid & 31, g = lane >> 2, t4 = lane & 3;
    const int wr = w >> 2, wc = w & 3;
    const int mBase = blockIdx.y * 128;
    const int nBase = blockIdx.x * 128;

    float acc[4][4][4] = {};

    // stage: A 128 rows x 128 B + B 128 rows x 128 B, stride 144
    auto loadStage = [&](int kt, int s) {
        char* St = smc + s * GH_STGB;
        const int k0 = kt * GH_BK;
        #pragma unroll
        for (int i = 0; i < 4; i++) {      // A: 1024 16B chunks
            int id = tid + i * 256;
            int r = id >> 3, c = id & 7;
            cp16(St + r * GH_ROWB + c * 16,
                 A + (size_t)(mBase + r) * K + k0 + c * 8);
        }
        #pragma unroll
        for (int i = 0; i < 4; i++) {      // B: 1024 16B chunks
            int id = tid + i * 256;
            int r = id >> 3, c = id & 7;
            cp16(St + (128 + r) * GH_ROWB + c * 16,
                 Wt + (size_t)(nBase + r) * K + k0 + c * 8);
        }
    };

    const int nIter = K / GH_BK;   // 32
    loadStage(0, 0); cp_commit();
    loadStage(1, 1); cp_commit();

    const int aRow = wr * 64 + (lane & 15);
    const int aChunk = (lane >> 4) << 4;
    const int li = lane >> 3;
    const int bRowOff = ((li >> 1) << 3) + (lane & 7);
    const int bChunk = (li & 1) << 4;

    for (int kt = 0; kt < nIter; kt++) {
        cp_wait<1>();
        __syncthreads();

        const int nt = kt + 2;
        if (nt < nIter) loadStage(nt, nt % 3);
        cp_commit();

        const uint32_t Ab = sbase + (kt % 3) * GH_STGB;
        const uint32_t Bb = Ab + 128 * GH_ROWB;

        #pragma unroll
        for (int k16 = 0; k16 < 4; k16++) {
            uint32_t af[4][4], bf[2][4];
            #pragma unroll
            for (int mi = 0; mi < 4; mi++)
                ldmx4(af[mi], Ab + (aRow + mi * 16) * GH_ROWB + aChunk + k16 * 32);
            #pragma unroll
            for (int np = 0; np < 2; np++)
                ldmx4(bf[np], Bb + (wc * 32 + np * 16 + bRowOff) * GH_ROWB
                              + bChunk + k16 * 32);
            #pragma unroll
            for (int mi = 0; mi < 4; mi++)
                #pragma unroll
                for (int np = 0; np < 2; np++) {
                    mma_f16(acc[mi][np * 2 + 0], af[mi], bf[np][0], bf[np][1]);
                    mma_f16(acc[mi][np * 2 + 1], af[mi], bf[np][2], bf[np][3]);
                }
        }
    }

    #pragma unroll
    for (int mi = 0; mi < 4; mi++) {
        #pragma unroll
        for (int r2 = 0; r2 < 2; r2++) {
            const int m = mBase + wr * 64 + mi * 16 + g + r2 * 8;
            #pragma unroll
            for (int ni = 0; ni < 4; ni++) {
                const int n = nBase + wc * 32 + ni * 8 + 2 * t4;
                if (FUSED) {
                    const int which = n >> 11;        // 0=Q 1=K 2=V
                    const int n2 = n & (H_ - 1);
                    const float* bias = (which == 0) ? b0v : (which == 1) ? b1v : b2v;
                    __half* dst = (which == 0) ? o0 : (which == 1) ? o1 : o2;
                    const int b = m >> 11;
                    const int s = m & (S_ - 1);
                    const int h = n2 >> 7;
                    const int d = n2 & (HD_ - 1);
                    uint32_t pv = packh2(acc[mi][ni][r2 * 2 + 0] + bias[n2],
                                         acc[mi][ni][r2 * 2 + 1] + bias[n2 + 1]);
                    *(uint32_t*)&dst[(((size_t)(b * NH_ + h)) * S_ + s) * HD_ + d] = pv;
                } else {
                    float2 v;
                    v.x = acc[mi][ni][r2 * 2 + 0] + b0v[n];
                    v.y = acc[mi][ni][r2 * 2 + 1] + b0v[n + 1];
                    *(float2*)&of[(size_t)m * H_ + n] = v;
                }
            }
        }
    }
}

// ---------------------------------------------------------------------------
// fp16 flash attention, BKT=64, double-buffered K/V (Round 9 — measured win).
// ---------------------------------------------------------------------------
#define AT_BK   64
#define AQ_ROWB 272
#define AT_KVB  (AT_BK * AQ_ROWB)                              // 17408 B
#define AT_SMEM (128 * AQ_ROWB + 4 * AT_KVB + 2 * AT_BK * 4)   // 104960 B

__global__ __launch_bounds__(256, 2)
void attn_h(const __half* __restrict__ Q, const __half* __restrict__ K,
            const __half* __restrict__ V, const float* __restrict__ mask,
            __half* __restrict__ out)
{
    extern __shared__ char smc[];
    char* Qs = smc;                              // 128 x 272 B
    char* KV = Qs + 128 * AQ_ROWB;               // 2 x (K 64x272 + V 64x272)
    float* msk = (float*)(KV + 4 * AT_KVB);      // 2 x 64 floats
    const uint32_t qbase  = smem_u32(Qs);
    const uint32_t kvbase = smem_u32(KV);

    const int tid = threadIdx.x;
    const int w = tid >> 5, lane = tid & 31, g = lane >> 2, t4 = lane & 3;
    const int bh = blockIdx.y;
    const int b  = bh >> 4;
    const int q0 = blockIdx.x * 128;

    const __half* Qg = Q + ((size_t)bh * S_ + q0) * HD_;
    const __half* Kg = K + (size_t)bh * S_ * HD_;
    const __half* Vg = V + (size_t)bh * S_ * HD_;
    const float* maskg = mask + (size_t)b * S_;

    #pragma unroll
    for (int i = 0; i < 8; i++) {
        int id = tid + i * 256;
        int r = id >> 4, c = id & 15;
        cp16(Qs + r * AQ_ROWB + c * 16, Qg + (size_t)r * HD_ + c * 8);
    }
    auto loadKV = [&](int kb0, int buf) {
        char* Kb = KV + buf * 2 * AT_KVB;
        char* Vb = Kb + AT_KVB;
        #pragma unroll
        for (int i = 0; i < 4; i++) {
            int id = tid + i * 256;
            int r = id >> 4, c = id & 15;
            cp16(Kb + r * AQ_ROWB + c * 16, Kg + (size_t)(kb0 + r) * HD_ + c * 8);
            cp16(Vb + r * AQ_ROWB + c * 16, Vg + (size_t)(kb0 + r) * HD_ + c * 8);
        }
        if (tid < AT_BK) msk[buf * AT_BK + tid] = maskg[kb0 + tid];
    };
    loadKV(0, 0);       cp_commit();   // G0 (incl. Q)
    loadKV(AT_BK, 1);   cp_commit();   // G1

    float O[16][4];
    #pragma unroll
    for (int nt = 0; nt < 16; nt++)
        #pragma unroll
        for (int c = 0; c < 4; c++) O[nt][c] = 0.f;
    float m_lo = -1e30f, m_hi = -1e30f, l_lo = 0.f, l_hi = 0.f;

    const float scale = 0.08838834764831845f;   // 1/sqrt(128)
    const int nIter = S_ / AT_BK;               // 32

    const int aRow = (lane & 15);
    const int aChunk = (lane >> 4) << 4;
    const int li = lane >> 3;
    const int bRowOff = ((li >> 1) << 3) + (lane & 7);
    const int bChunk = (li & 1) << 4;
    const uint32_t qaddr0 = qbase + (w * 16 + aRow) * AQ_ROWB + aChunk;

    for (int kt = 0; kt < nIter; kt++) {
        cp_wait<1>();                  // buffer kt&1 loads complete
        __syncthreads();

        const int buf = kt & 1;
        const uint32_t kbase = kvbase + buf * 2 * AT_KVB;
        const uint32_t vbase = kbase + AT_KVB;
        const float* mk = msk + buf * AT_BK;

        // ---- S = Q @ K^T (16x64 per warp), 8 k16 steps ----
        float sacc[8][4] = {};
        #pragma unroll
        for (int k16 = 0; k16 < 8; k16++) {
            uint32_t af[4], bf[4][4];
            ldmx4(af, qaddr0 + k16 * 32);
            #pragma unroll
            for (int np = 0; np < 4; np++)
                ldmx4(bf[np], kbase + (np * 16 + bRowOff) * AQ_ROWB
                              + bChunk + k16 * 32);
            #pragma unroll
            for (int np = 0; np < 4; np++) {
                mma_f16(sacc[np * 2 + 0], af, bf[np][0], bf[np][1]);
                mma_f16(sacc[np * 2 + 1], af, bf[np][2], bf[np][3]);
            }
        }

        // ---- scale + mask ----
        #pragma unroll
        for (int ni = 0; ni < 8; ni++)
            #pragma unroll
            for (int c = 0; c < 4; c++) {
                const int col = ni * 8 + 2 * t4 + (c & 1);
                sacc[ni][c] = sacc[ni][c] * scale + mk[col];
            }

        // ---- in-warp softmax ----
        float rm_lo = -1e30f, rm_hi = -1e30f;
        #pragma unroll
        for (int ni = 0; ni < 8; ni++) {
            rm_lo = fmaxf(rm_lo, fmaxf(sacc[ni][0], sacc[ni][1]));
            rm_hi = fmaxf(rm_hi, fmaxf(sacc[ni][2], sacc[ni][3]));
        }
        rm_lo = fmaxf(rm_lo, __shfl_xor_sync(0xffffffffu, rm_lo, 1));
        rm_lo = fmaxf(rm_lo, __shfl_xor_sync(0xffffffffu, rm_lo, 2));
        rm_hi = fmaxf(rm_hi, __shfl_xor_sync(0xffffffffu, rm_hi, 1));
        rm_hi = fmaxf(rm_hi, __shfl_xor_sync(0xffffffffu, rm_hi, 2));

        const float mn_lo = fmaxf(m_lo, rm_lo);
        const float mn_hi = fmaxf(m_hi, rm_hi);
        const float al_lo = __expf(m_lo - mn_lo);
        const float al_hi = __expf(m_hi - mn_hi);
        m_lo = mn_lo;
        m_hi = mn_hi;

        float sum_lo = 0.f, sum_hi = 0.f;
        #pragma unroll
        for (int ni = 0; ni < 8; ni++) {
            sacc[ni][0] = __expf(sacc[ni][0] - mn_lo);
            sacc[ni][1] = __expf(sacc[ni][1] - mn_lo);
            sacc[ni][2] = __expf(sacc[ni][2] - mn_hi);
            sacc[ni][3] = __expf(sacc[ni][3] - mn_hi);
            sum_lo += sacc[ni][0] + sacc[ni][1];
            sum_hi += sacc[ni][2] + sacc[ni][3];
        }
        sum_lo += __shfl_xor_sync(0xffffffffu, sum_lo, 1);
        sum_lo += __shfl_xor_sync(0xffffffffu, sum_lo, 2);
        sum_hi += __shfl_xor_sync(0xffffffffu, sum_hi, 1);
        sum_hi += __shfl_xor_sync(0xffffffffu, sum_hi, 2);
        l_lo = l_lo * al_lo + sum_lo;
        l_hi = l_hi * al_hi + sum_hi;

        #pragma unroll
        for (int nt = 0; nt < 16; nt++) {
            O[nt][0] *= al_lo;  O[nt][1] *= al_lo;
            O[nt][2] *= al_hi;  O[nt][3] *= al_hi;
        }

        // ---- O += P @ V ----
        #pragma unroll
        for (int kb = 0; kb < 4; kb++) {
            uint32_t af[4];
            af[0] = packh2(sacc[2 * kb][0],     sacc[2 * kb][1]);
            af[1] = packh2(sacc[2 * kb][2],     sacc[2 * kb][3]);
            af[2] = packh2(sacc[2 * kb + 1][0], sacc[2 * kb + 1][1]);
            af[3] = packh2(sacc[2 * kb + 1][2], sacc[2 * kb + 1][3]);
            #pragma unroll
            for (int t = 0; t < 8; t++) {
                uint32_t bf[4];
                ldmx4t(bf, vbase + (kb * 16 + aRow) * AQ_ROWB
                           + (2 * t) * 16 + aChunk);
                mma_f16(O[2 * t + 0], af, bf[0], bf[1]);
                mma_f16(O[2 * t + 1], af, bf[2], bf[3]);
            }
        }

        __syncthreads();               // all warps done with buf before refill
        const int nt2 = kt + 2;
        if (nt2 < nIter) loadKV(nt2 * AT_BK, buf);
        cp_commit();                   // unconditional (group accounting)
    }

    // ---- finalize ----
    const int h = bh & (NH_ - 1);
    const float inv_lo = 1.f / l_lo;
    const float inv_hi = 1.f / l_hi;
    const int q_lo = q0 + w * 16 + g;
    __half* dst_lo = out + ((size_t)b * S_ + q_lo) * H_ + h * HD_;
    __half* dst_hi = dst_lo + (size_t)8 * H_;
    #pragma unroll
    for (int nt = 0; nt < 16; nt++) {
        const int col = nt * 8 + 2 * t4;
        *(uint32_t*)&dst_lo[col] = packh2(O[nt][0] * inv_lo, O[nt][1] * inv_lo);
        *(uint32_t*)&dst_hi[col] = packh2(O[nt][2] * inv_hi, O[nt][3] * inv_hi);
    }
}

// ---------------------------------------------------------------------------
// Launch
// ---------------------------------------------------------------------------
extern "C" void kernel_launch(void* const* d_in, const int* in_sizes, int n_in,
                              void* d_out, int out_size)
{
    const float* x    = (const float*)d_in[0];
    const float* mask = (const float*)d_in[1];
    const float* Wq   = (const float*)d_in[2];
    const float* bq   = (const float*)d_in[3];
    const float* Wk   = (const float*)d_in[4];
    const float* bk   = (const float*)d_in[5];
    const float* Wv   = (const float*)d_in[6];
    const float* bv   = (const float*)d_in[7];
    const float* Wo   = (const float*)d_in[8];
    const float* bo   = (const float*)d_in[9];
    float* out = (float*)d_out;

    __half *q, *k, *v, *attn, *xh, *wt;
    cudaGetSymbolAddress((void**)&q,    g_q);
    cudaGetSymbolAddress((void**)&k,    g_k);
    cudaGetSymbolAddress((void**)&v,    g_v);
    cudaGetSymbolAddress((void**)&attn, g_attn);
    cudaGetSymbolAddress((void**)&xh,   g_xh);
    cudaGetSymbolAddress((void**)&wt,   g_wt);

    cudaFuncSetAttribute(gemm_h<true>,
                         cudaFuncAttributeMaxDynamicSharedMemorySize, GH_SMEM);
    cudaFuncSetAttribute(gemm_h<false>,
                         cudaFuncAttributeMaxDynamicSharedMemorySize, GH_SMEM);
    cudaFuncSetAttribute(attn_h,
                         cudaFuncAttributeMaxDynamicSharedMemorySize, AT_SMEM);

    // Prep: x -> fp16; all 4 weights transposed in one launch
    const int nx4 = MTOT * H_ / 4;
    halfcast<<<(nx4 + 255) / 256, 256>>>(x, xh, nx4);
    transpose_half4<<<dim3(H_ / 32, H_ / 32, 4), dim3(32, 8)>>>(Wq, Wk, Wv, Wo, wt);

    const size_t wsz = (size_t)H_ * H_;

    // Fused QKV projection (N = 3*2048, 128x128 tiles, BK=64)
    gemm_h<true><<<dim3(3 * H_ / 128, MTOT / 128), 256, GH_SMEM>>>(
        xh, wt, bq, bk, bv, q, k, v, nullptr);

    attn_h<<<dim3(S_ / 128, B_ * NH_), 256, AT_SMEM>>>(q, k, v, mask, attn);

    // Out projection (fp32 output)
    gemm_h<false><<<dim3(H_ / 128, MTOT / 128), 256, GH_SMEM>>>(
        attn, wt + 3 * wsz, bo, nullptr, nullptr,
        nullptr, nullptr, nullptr, out);
}